// round 7
// baseline (speedup 1.0000x reference)
#include <cuda_runtime.h>

#define A_TOTAL 76725
#define NCLS 80
#define KTOP 1000
#define NB 4096
#define CAND 2048
#define IMGF 640.0f

// scratch
__device__ float4 g_boxes4[A_TOTAL];
__device__ float g_clsT[(size_t)NCLS * A_TOTAL];  // transposed scores [C][A]

// -------------------- Kernel 1: decode + clip boxes --------------------
__global__ void decode_kernel(const float* __restrict__ reg,
                              const float* __restrict__ anc) {
    int a = blockIdx.x * blockDim.x + threadIdx.x;
    if (a >= A_TOTAL) return;
    float a0 = anc[a * 4 + 0], a1 = anc[a * 4 + 1];
    float a2 = anc[a * 4 + 2], a3 = anc[a * 4 + 3];
    float aw = a2 - a0, ah = a3 - a1;
    float cx = a0 + 0.5f * aw, cy = a1 + 0.5f * ah;
    float dx = reg[a * 4 + 0] * 0.1f;
    float dy = reg[a * 4 + 1] * 0.1f;
    float dw = reg[a * 4 + 2] * 0.2f;
    float dh = reg[a * 4 + 3] * 0.2f;
    float pcx = cx + dx * aw;
    float pcy = cy + dy * ah;
    float pw = expf(dw) * aw;
    float ph = expf(dh) * ah;
    float4 b;
    b.x = fmaxf(pcx - 0.5f * pw, 0.0f);
    b.y = fmaxf(pcy - 0.5f * ph, 0.0f);
    b.z = fminf(pcx + 0.5f * pw, IMGF);
    b.w = fminf(pcy + 0.5f * ph, IMGF);
    g_boxes4[a] = b;
}

// -------------------- Kernel 2: transpose scores --------------------
// cls [A,80] row-major -> clsT [80,A]; tiled, coalesced both sides
__global__ void transpose_kernel(const float* __restrict__ cls) {
    __shared__ float tile[32][33];
    int a0 = blockIdx.x * 32;
    int c0 = blockIdx.y * 32;
    int tx = threadIdx.x, ty = threadIdx.y;  // block 32x8
#pragma unroll
    for (int i = 0; i < 32; i += 8) {
        int a = a0 + ty + i, c = c0 + tx;
        if (a < A_TOTAL && c < NCLS) tile[ty + i][tx] = cls[(size_t)a * NCLS + c];
    }
    __syncthreads();
#pragma unroll
    for (int i = 0; i < 32; i += 8) {
        int c = c0 + ty + i, a = a0 + tx;
        if (a < A_TOTAL && c < NCLS)
            g_clsT[(size_t)c * A_TOTAL + a] = tile[tx][ty + i];
    }
}

// ---------- Kernel 3: per-class top-K select + sort + NMS + output ----------
__global__ __launch_bounds__(1024) void topk_nms_kernel(float* __restrict__ out) {
    __shared__ unsigned long long s_cand[CAND];  // 16 KB
    __shared__ float s_over[NB];                 // 16 KB: hist (int) then boxes
    __shared__ float s_area[KTOP];               // 4 KB
    __shared__ int s_keep[1024];                 // 4 KB
    __shared__ unsigned s_cmask[32];
    __shared__ int s_chunk[128];
    __shared__ int s_misc[2];

    int* hist = (int*)s_over;
    float* s_box = s_over;
    const int tid = threadIdx.x;
    const int c = blockIdx.x;
    const float* __restrict__ col = g_clsT + (size_t)c * A_TOTAL;

    // ---- phase 1: histogram (coalesced reads) ----
    for (int b = tid; b < NB; b += 1024) hist[b] = 0;
    __syncthreads();
    for (int a = tid; a < A_TOTAL; a += 1024) {
        float s = col[a];
        int b = (int)(s * (float)NB);
        b = min(max(b, 0), NB - 1);
        atomicAdd(&hist[b], 1);
    }
    __syncthreads();

    // ---- phase 2: threshold bucket B ----
    if (tid < 128) {
        int sum = 0;
#pragma unroll
        for (int b = 0; b < 32; b++) sum += hist[tid * 32 + b];
        s_chunk[tid] = sum;
    }
    __syncthreads();
    if (tid == 0) {
        int acc = 0;
        int ch = 127;
        for (; ch > 0; ch--) {
            if (acc + s_chunk[ch] >= KTOP) break;
            acc += s_chunk[ch];
        }
        int B = ch * 32;
        for (int b = ch * 32 + 31; b >= ch * 32; b--) {
            acc += hist[b];
            if (acc >= KTOP) { B = b; break; }
        }
        s_misc[0] = B;
        s_misc[1] = 0;
    }
    __syncthreads();
    const int B = s_misc[0];

    // ---- phase 3: gather candidates ----
    s_cand[tid] = 0ULL;
    s_cand[tid + 1024] = 0ULL;
    __syncthreads();
    for (int a = tid; a < A_TOTAL; a += 1024) {
        float s = col[a];
        int b = (int)(s * (float)NB);
        b = min(max(b, 0), NB - 1);
        if (b >= B) {
            int pos = atomicAdd(&s_misc[1], 1);
            if (pos < CAND) {
                unsigned sb = __float_as_uint(s);
                s_cand[pos] = ((unsigned long long)sb << 32) |
                              (unsigned long long)(0xFFFFFFFFu - (unsigned)a);
            }
        }
    }
    __syncthreads();

    // ---- phase 4: bitonic sort (descending) ----
    for (unsigned k = 2; k <= CAND; k <<= 1) {
        for (unsigned j = k >> 1; j > 0; j >>= 1) {
#pragma unroll
            for (unsigned base = 0; base < CAND; base += 1024) {
                unsigned e = base + tid;
                unsigned ix = e ^ j;
                if (ix > e) {
                    unsigned long long x = s_cand[e];
                    unsigned long long y = s_cand[ix];
                    bool desc = ((e & k) == 0);
                    bool sw = desc ? (x < y) : (x > y);
                    if (sw) { s_cand[e] = y; s_cand[ix] = x; }
                }
            }
            __syncthreads();
        }
    }

    // ---- phase 5: extract top-K ----
    float mx1 = 0.f, my1 = 0.f, mx2 = 0.f, my2 = 0.f;
    float myarea = 0.f, myscore = 0.f;
    bool mykeep = false;
    if (tid < KTOP) {
        unsigned long long key = s_cand[tid];
        myscore = __uint_as_float((unsigned)(key >> 32));
        unsigned idx = 0xFFFFFFFFu - (unsigned)(key & 0xFFFFFFFFu);
        float4 bx = g_boxes4[idx];
        mx1 = bx.x; my1 = bx.y; mx2 = bx.z; my2 = bx.w;
        myarea = (mx2 - mx1) * (my2 - my1);
        mykeep = (myscore > 0.001f);
    }
    __syncthreads();
    if (tid < KTOP) {
        s_box[tid * 4 + 0] = mx1;
        s_box[tid * 4 + 1] = my1;
        s_box[tid * 4 + 2] = mx2;
        s_box[tid * 4 + 3] = my2;
        s_area[tid] = myarea;
    }
    s_keep[tid] = (tid < KTOP && mykeep) ? 1 : 0;
    __syncthreads();

    // ---- phase 6: chunked greedy NMS (32 boxes per chunk) ----
    const int NCH = (KTOP + 31) / 32;  // 32
    for (int cb = 0; cb < NCH; cb++) {
        const int base = cb * 32;
        // step 1: chunk members build intra-chunk suppression masks
        if (tid >= base && tid < base + 32) {
            unsigned msk = 0;
            if (mykeep) {
#pragma unroll 4
                for (int m = 0; m < 32; m++) {
                    int j = base + m;
                    if (j < KTOP && s_keep[j]) {
                        float lx = fmaxf(mx1, s_box[j * 4 + 0]);
                        float ly = fmaxf(my1, s_box[j * 4 + 1]);
                        float rx = fminf(mx2, s_box[j * 4 + 2]);
                        float ry = fminf(my2, s_box[j * 4 + 3]);
                        float w = fmaxf(rx - lx, 0.0f);
                        float h = fmaxf(ry - ly, 0.0f);
                        float inter = w * h;
                        float iou = inter / (s_area[j] + myarea - inter + 1e-8f);
                        if (iou > 0.5f) msk |= (1u << m);
                    }
                }
            }
            s_cmask[tid - base] = msk;
        }
        __syncthreads();
        // step 2: resolve chunk keep bits (redundant on all threads, registers only)
        unsigned keptbits = 0, supp = 0;
#pragma unroll 4
        for (int m = 0; m < 32; m++) {
            int j = base + m;
            bool km = (j < KTOP) && s_keep[j] && !((supp >> m) & 1u);
            if (km) {
                keptbits |= (1u << m);
                supp |= s_cmask[m] & ~((2u << m) - 1u);  // only later boxes
            }
        }
        // step 3: later boxes test against kept chunk members only
        if (mykeep && tid < KTOP) {
            if (tid >= base && tid < base + 32) {
                mykeep = (keptbits >> (tid - base)) & 1u;
            } else if (tid >= base + 32) {
                unsigned rel = keptbits;
                while (rel) {
                    int m = __ffs(rel) - 1;
                    rel &= rel - 1;
                    int j = base + m;
                    float lx = fmaxf(mx1, s_box[j * 4 + 0]);
                    float ly = fmaxf(my1, s_box[j * 4 + 1]);
                    float rx = fminf(mx2, s_box[j * 4 + 2]);
                    float ry = fminf(my2, s_box[j * 4 + 3]);
                    float w = fmaxf(rx - lx, 0.0f);
                    float h = fmaxf(ry - ly, 0.0f);
                    float inter = w * h;
                    float iou = inter / (s_area[j] + myarea - inter + 1e-8f);
                    if (iou > 0.5f) { mykeep = false; break; }
                }
            }
        }
        __syncthreads();  // step2/3 reads of s_keep/s_cmask done
        s_keep[tid] = mykeep ? 1 : 0;
        __syncthreads();  // publish before next chunk reads
    }

    // ---- phase 7: outputs ----
    if (tid < KTOP) {
        float kf = mykeep ? 1.0f : 0.0f;
        int o = c * KTOP + tid;
        const int CK = NCLS * KTOP;
        out[o] = myscore * kf;
        out[CK + o] = (float)c;
        out[2 * CK + o * 4 + 0] = mx1 * kf;
        out[2 * CK + o * 4 + 1] = my1 * kf;
        out[2 * CK + o * 4 + 2] = mx2 * kf;
        out[2 * CK + o * 4 + 3] = my2 * kf;
        out[6 * CK + o] = kf;
    }
}

extern "C" void kernel_launch(void* const* d_in, const int* in_sizes, int n_in,
                              void* d_out, int out_size) {
    const float* cls = (const float*)d_in[1];
    const float* reg = (const float*)d_in[2];
    const float* anc = (const float*)d_in[3];
    float* out = (float*)d_out;

    decode_kernel<<<(A_TOTAL + 255) / 256, 256>>>(reg, anc);
    dim3 tgrid((A_TOTAL + 31) / 32, (NCLS + 31) / 32);
    transpose_kernel<<<tgrid, dim3(32, 8)>>>(cls);
    topk_nms_kernel<<<NCLS, 1024>>>(out);
}